// round 5
// baseline (speedup 1.0000x reference)
#include <cuda_runtime.h>
#include <math.h>

// ---------------------------------------------------------------------------
// DCTModel collapsed: out[b, cq*54+m(u,v), i, j] =
//   sum_{r,s<3} W[i][u][r] * W[j][v][s] * t[b,cq, base_i+r, base_j+s]
// t = 127.5 * (RGB2YCBCR @ x). Additive constants only hit the dropped DC.
//
// R4: epilogue column weights precomputed as padded/shifted 4-vectors
// (g_W4[j][8][4], odd j pre-shifted to the even partner's base) -> no gb copy,
// no selects, float4 LDS with conflict-free 68-float pair stride. Init kernel
// uses an exact cos(k*pi/16) literal table (no fp64 cos).
// ---------------------------------------------------------------------------

#define HW 112
#define NPLANE 12544
#define NBATCH 16

#define BX 56           // j-pairs per block
#define BY 4            // i rows per block
#define NTHREADS (BX*BY)
#define ROWS_T 6
#define COLS_T 114
#define PSTRIDE 68      // floats per pair in sW4 (64 data + 4 pad) -> bank step 4

__device__ float g_W [HW][8][3];   // row weights
__device__ float g_W4[HW][8][4];   // column weights, padded/pre-shifted per pair
__device__ int   g_base[HW];

__constant__ float c_M[3][3] = {
    { 0.299f,     0.587f,    0.114f    },
    {-0.168736f, -0.331264f, 0.5f      },
    { 0.5f,      -0.418688f, -0.081312f}
};

// SUB_CHANNELS = {0,1,2,3,4,5,8,9,16,24}
#define SUB_MASK 0x000000000101033FULL

// ---------------------------------------------------------------------------
// Exact cos(k*pi/16) via literal table + symmetry (no transcendentals).
// ---------------------------------------------------------------------------
__device__ __forceinline__ double cos_pi16(int k) {
    const double T[9] = {
        1.0,
        0.98078528040323044913,  // cos(pi/16)
        0.92387953251128675613,  // cos(2pi/16)
        0.83146961230254523708,
        0.70710678118654752440,
        0.55557023301960222474,
        0.38268343236508977173,
        0.19509032201612826785,
        0.0
    };
    k &= 31;
    if (k > 16) k = 32 - k;
    double s = 1.0;
    if (k > 8) { s = -1.0; k = 16 - k; }
    return s * T[k];
}

__global__ void init_weights_kernel() {
    int i = threadIdx.x;
    if (i >= HW) return;

    // numpy float64 src/floor/clamp, mirrored exactly
    int    i0[8];
    double w[8];
    int base = 1 << 30;
    #pragma unroll
    for (int x = 0; x < 8; x++) {
        int o = 8 * i + x;
        double src = ((double)o * 111.0) / 895.0;
        int f = (int)floor(src);
        if (f > HW - 2) f = HW - 2;
        i0[x] = f;
        w[x]  = src - (double)f;
        if (f < base) base = f;
    }
    g_base[i] = base;

    double a[8][3];
    #pragma unroll
    for (int x = 0; x < 8; x++) { a[x][0] = a[x][1] = a[x][2] = 0.0; }
    #pragma unroll
    for (int x = 0; x < 8; x++) {
        int off = i0[x] - base;
        a[x][off]     += 1.0 - w[x];
        a[x][off + 1] += w[x];
    }

    const double ISQ2 = 0.70710678118654752440;
    #pragma unroll
    for (int u = 0; u < 8; u++) {
        double alpha = (u == 0) ? ISQ2 : 1.0;
        #pragma unroll
        for (int r = 0; r < 3; r++) {
            double s = 0.0;
            #pragma unroll
            for (int x = 0; x < 8; x++)
                s += cos_pi16((2 * x + 1) * u) * a[x][r];
            g_W[i][u][r] = (float)(s * alpha * 0.5);
        }
    }
    __syncthreads();

    // Padded column-weight 4-vectors relative to the pair's even-j base.
    // shift = base[j] - base[j & ~1] in {0,1}; W4[v][shift+k] = W[j][v][k].
    int shift = base - g_base[i & ~1];
    #pragma unroll
    for (int v = 0; v < 8; v++) {
        float w4[4] = {0.f, 0.f, 0.f, 0.f};
        #pragma unroll
        for (int k = 0; k < 3; k++) w4[shift + k] = g_W[i][v][k];
        #pragma unroll
        for (int s = 0; s < 4; s++) g_W4[i][v][s] = w4[s];
    }
}

// ---------------------------------------------------------------------------
// Main: block = (56 j-pairs, 4 i-rows); grid = (28, 3 cq, 16 b).
// ---------------------------------------------------------------------------
__global__ __launch_bounds__(NTHREADS, 4)
void dct_main_kernel(const float* __restrict__ x, float* __restrict__ out) {
    __shared__ __align__(16) float sW4[BX * PSTRIDE]; // 15.2 KB, pair-interleaved
    __shared__ float sR[BY * 25];                     // row weights (padded)
    __shared__ float sT[ROWS_T * COLS_T];             // YCbCr tile
    __shared__ int   sB[HW];

    const int tx  = threadIdx.x;            // 0..55 (j-pair)
    const int ty  = threadIdx.y;            // 0..3
    const int tid = ty * BX + tx;
    const int cq  = blockIdx.y;
    const int b   = blockIdx.z;
    const int i0  = blockIdx.x * BY;

    const int rmin = __ldg(&g_base[i0]);

    // ---- cooperative smem fill -------------------------------------------
    // sW4: pair p holds [v][sel][s] at p*68 + v*8 + sel*4 + s
    const float* gw4 = &g_W4[0][0][0];
    for (int e = tid; e < BX * 64; e += NTHREADS) {
        int p = e >> 6, rem = e & 63;
        int v = rem >> 3, sel = (rem >> 2) & 1, s = rem & 3;
        sW4[p * PSTRIDE + rem] = gw4[(2 * p + sel) * 32 + v * 4 + s];
    }
    if (tid < BY * 24) {
        int r = tid / 24, rem = tid - r * 24;
        sR[r * 25 + rem] = (&g_W[0][0][0])[(i0 + r) * 24 + rem];
    }
    if (tid < HW) sB[tid] = g_base[tid];

    {
        const float m0 = 127.5f * c_M[cq][0];
        const float m1 = 127.5f * c_M[cq][1];
        const float m2 = 127.5f * c_M[cq][2];
        const float* xb = x + (size_t)b * 3 * NPLANE;
        for (int e = tid; e < ROWS_T * COLS_T; e += NTHREADS) {
            int lr = e / COLS_T, c = e - lr * COLS_T;
            int srow = rmin + lr; if (srow > HW - 1) srow = HW - 1;
            int scol = c;         if (scol > HW - 1) scol = HW - 1;
            int off = srow * HW + scol;
            float p0 = __ldg(xb + off);
            float p1 = __ldg(xb + NPLANE + off);
            float p2 = __ldg(xb + 2 * NPLANE + off);
            sT[e] = fmaf(m0, p0, fmaf(m1, p1, m2 * p2));
        }
    }
    __syncthreads();

    // ---- per-thread work --------------------------------------------------
    const int i   = i0 + ty;
    const int j0  = 2 * tx;
    const int bj0 = sB[j0];                 // pair base (even j)
    const int lr  = sB[i] - rmin;           // 0..3

    // 3x4 patch
    float t[3][4];
    #pragma unroll
    for (int r = 0; r < 3; r++) {
        const float* row = &sT[(lr + r) * COLS_T + bj0];
        #pragma unroll
        for (int s = 0; s < 4; s++) t[r][s] = row[s];
    }

    // gv[u][s] = sum_r W[i][u][r] * t[r][s]
    float gv[8][4];
    {
        const float* wr = &sR[ty * 25];
        #pragma unroll
        for (int u = 0; u < 8; u++) {
            float w0 = wr[u * 3 + 0], w1 = wr[u * 3 + 1], w2 = wr[u * 3 + 2];
            #pragma unroll
            for (int s = 0; s < 4; s++)
                gv[u][s] = fmaf(w0, t[0][s], fmaf(w1, t[1][s], w2 * t[2][s]));
        }
    }

    // Epilogue: 27 float2 stores; two 4-wide dots per (u,v)
    float* outp = out + ((size_t)(b * 162 + cq * 54)) * NPLANE + i * HW + j0;
    const float* wp = &sW4[tx * PSTRIDE];

    #pragma unroll
    for (int v = 0; v < 8; v++) {
        const float4 wa = *reinterpret_cast<const float4*>(wp + v * 8);
        const float4 wb = *reinterpret_cast<const float4*>(wp + v * 8 + 4);
        #pragma unroll
        for (int u = 0; u < 8; u++) {
            const int idx = u * 8 + v;
            if ((SUB_MASK >> idx) & 1ULL) continue;
            const int m = idx - __popcll(SUB_MASK & ((1ULL << idx) - 1ULL));
            float2 val;
            val.x = fmaf(gv[u][0], wa.x, fmaf(gv[u][1], wa.y,
                    fmaf(gv[u][2], wa.z, gv[u][3] * wa.w)));
            val.y = fmaf(gv[u][0], wb.x, fmaf(gv[u][1], wb.y,
                    fmaf(gv[u][2], wb.z, gv[u][3] * wb.w)));
            *reinterpret_cast<float2*>(outp + (size_t)m * NPLANE) = val;
        }
    }
}

// ---------------------------------------------------------------------------
extern "C" void kernel_launch(void* const* d_in, const int* in_sizes, int n_in,
                              void* d_out, int out_size) {
    const float* x = (const float*)d_in[0];   // (16, 3, 112, 112) fp32
    float* out = (float*)d_out;               // (16, 162, 112, 112) fp32

    init_weights_kernel<<<1, 128>>>();

    dim3 block(BX, BY);                       // 224 threads
    dim3 grid(HW / BY, 3, NBATCH);            // (28, 3, 16)
    dct_main_kernel<<<grid, block>>>(x, out);
}

// round 7
// speedup vs baseline: 1.5358x; 1.5358x over previous
#include <cuda_runtime.h>
#include <math.h>

// ---------------------------------------------------------------------------
// DCTModel collapsed to a single kernel:
//   out[b, cq*54+m(u,v), i, j] =
//     sum_{r,s<3} W[i][u][r] * W[j][v][s] * t[b,cq, base_i+r, base_j+s]
//   t = 127.5 * (RGB2YCBCR @ x);  additive constants only hit the dropped DC.
//
// R5: init kernel eliminated (it + the 2-node graph gap cost ~9us of the
// 44.6us total). Each block rebuilds its weights in fp32 with compile-time
// cos(k*pi/16) immediates: per column ~250 FMA on 112 threads, overlapped
// with the tile load. fp32 is safe: floor-decision margin of src=o*111/895
// is >=1/895 ~ 1.1e-3 vs fp32 error ~1e-5; o=895 divides exactly.
// ---------------------------------------------------------------------------

#define HW 112
#define NPLANE 12544
#define NBATCH 16

#define BX 56           // j-pairs per block
#define BY 4            // i rows per block
#define NTHREADS (BX*BY)
#define ROWS_T 6
#define COLS_T 114
#define PSTRIDE 68      // floats per pair in sW4 (64 data + 4 pad)

__constant__ float c_M[3][3] = {
    { 0.299f,     0.587f,    0.114f    },
    {-0.168736f, -0.331264f, 0.5f      },
    { 0.5f,      -0.418688f, -0.081312f}
};

// SUB_CHANNELS = {0,1,2,3,4,5,8,9,16,24}
#define SUB_MASK 0x000000000101033FULL

// ---------------------------------------------------------------------------
// cos(k*pi/16), constexpr -> folded to FFMA immediates in unrolled loops.
// ---------------------------------------------------------------------------
__host__ __device__ constexpr float cosw(int k) {
    const double T[9] = {
        1.0,
        0.98078528040323044913,
        0.92387953251128675613,
        0.83146961230254523708,
        0.70710678118654752440,
        0.55557023301960222474,
        0.38268343236508977173,
        0.19509032201612826785,
        0.0
    };
    k &= 31;
    if (k > 16) k = 32 - k;
    double s = 1.0;
    if (k > 8) { s = -1.0; k = 16 - k; }
    return (float)(s * T[k]);
}

// base index: src is monotone in x, so base = i0[x=0]
__device__ __forceinline__ int comp_base(int idx) {
    float src = (float)(8 * idx * 111) / 895.0f;
    int f = (int)floorf(src);
    return (f > HW - 2) ? (HW - 2) : f;
}

// Fused (DCT x upsample) weights for one block index: W[v][k], k<3.
__device__ __forceinline__ void comp_weights(int idx, float W[8][3]) {
    const int base = comp_base(idx);
    float A0[8], A1[8], A2[8];
    #pragma unroll
    for (int x = 0; x < 8; x++) {
        float src = (float)((8 * idx + x) * 111) / 895.0f;
        int f = (int)floorf(src);
        if (f > HW - 2) f = HW - 2;
        float w = src - (float)f;
        bool z = (f == base);           // offset 0 or 1
        A0[x] = z ? 1.0f - w : 0.0f;
        A1[x] = z ? w        : 1.0f - w;
        A2[x] = z ? 0.0f     : w;
    }
    #pragma unroll
    for (int v = 0; v < 8; v++) {
        float s0 = 0.f, s1 = 0.f, s2 = 0.f;
        #pragma unroll
        for (int x = 0; x < 8; x++) {
            const float c = cosw((2 * x + 1) * v);   // compile-time immediate
            s0 = fmaf(c, A0[x], s0);
            s1 = fmaf(c, A1[x], s1);
            s2 = fmaf(c, A2[x], s2);
        }
        const float sc = (v == 0) ? 0.35355339059327373f : 0.5f;  // alpha_v/2
        W[v][0] = s0 * sc; W[v][1] = s1 * sc; W[v][2] = s2 * sc;
    }
}

// ---------------------------------------------------------------------------
// Single kernel: block = (56 j-pairs, 4 i-rows); grid = (28, 3 cq, 16 b).
// ---------------------------------------------------------------------------
__global__ __launch_bounds__(NTHREADS, 4)
void dct_main_kernel(const float* __restrict__ x, float* __restrict__ out) {
    __shared__ __align__(16) float sW4[BX * PSTRIDE]; // 15.2 KB
    __shared__ float sR[BY * 25];                     // row weights (padded)
    __shared__ float sT[ROWS_T * COLS_T];             // YCbCr tile
    __shared__ int   sBp[BX];                         // even-j base per pair
    __shared__ int   sBi[BY];                         // row bases

    const int tx  = threadIdx.x;            // 0..55
    const int ty  = threadIdx.y;            // 0..3
    const int tid = ty * BX + tx;
    const int cq  = blockIdx.y;
    const int b   = blockIdx.z;
    const int i0  = blockIdx.x * BY;

    const int rmin = comp_base(i0);         // cheap, computed by every thread

    // ---- per-block weight construction (overlaps tile load) --------------
    if (tid < HW) {
        const int j = tid;
        float W[8][3];
        comp_weights(j, W);
        const int bj = comp_base(j);
        if ((j & 1) == 0) sBp[j >> 1] = bj;
        const bool sh = (bj - comp_base(j & ~1)) != 0;   // pair-relative shift
        float* dst = &sW4[(j >> 1) * PSTRIDE + (j & 1) * 4];
        #pragma unroll
        for (int v = 0; v < 8; v++) {
            dst[v * 8 + 0] = sh ? 0.0f    : W[v][0];
            dst[v * 8 + 1] = sh ? W[v][0] : W[v][1];
            dst[v * 8 + 2] = sh ? W[v][1] : W[v][2];
            dst[v * 8 + 3] = sh ? W[v][2] : 0.0f;
        }
    } else if (tid < HW + BY) {
        const int r = tid - HW;
        float W[8][3];
        comp_weights(i0 + r, W);
        #pragma unroll
        for (int u = 0; u < 8; u++) {
            sR[r * 25 + u * 3 + 0] = W[u][0];
            sR[r * 25 + u * 3 + 1] = W[u][1];
            sR[r * 25 + u * 3 + 2] = W[u][2];
        }
        sBi[r] = comp_base(i0 + r);
    }

    // ---- YCbCr tile (all threads) -----------------------------------------
    {
        const float m0 = 127.5f * c_M[cq][0];
        const float m1 = 127.5f * c_M[cq][1];
        const float m2 = 127.5f * c_M[cq][2];
        const float* xb = x + (size_t)b * 3 * NPLANE;
        for (int e = tid; e < ROWS_T * COLS_T; e += NTHREADS) {
            int lr = e / COLS_T, c = e - lr * COLS_T;
            int srow = rmin + lr; if (srow > HW - 1) srow = HW - 1;
            int scol = c;         if (scol > HW - 1) scol = HW - 1;
            int off = srow * HW + scol;
            float p0 = __ldg(xb + off);
            float p1 = __ldg(xb + NPLANE + off);
            float p2 = __ldg(xb + 2 * NPLANE + off);
            sT[e] = fmaf(m0, p0, fmaf(m1, p1, m2 * p2));
        }
    }
    __syncthreads();

    // ---- per-thread work --------------------------------------------------
    const int i   = i0 + ty;
    const int j0  = 2 * tx;
    const int bj0 = sBp[tx];
    const int lr  = sBi[ty] - rmin;          // 0..3

    float t[3][4];
    #pragma unroll
    for (int r = 0; r < 3; r++) {
        const float* row = &sT[(lr + r) * COLS_T + bj0];
        #pragma unroll
        for (int s = 0; s < 4; s++) t[r][s] = row[s];
    }

    // gv[u][s] = sum_r W[i][u][r] * t[r][s]
    float gv[8][4];
    {
        const float* wr = &sR[ty * 25];
        #pragma unroll
        for (int u = 0; u < 8; u++) {
            float w0 = wr[u * 3 + 0], w1 = wr[u * 3 + 1], w2 = wr[u * 3 + 2];
            #pragma unroll
            for (int s = 0; s < 4; s++)
                gv[u][s] = fmaf(w0, t[0][s], fmaf(w1, t[1][s], w2 * t[2][s]));
        }
    }

    // Epilogue: 27 float2 stores; two 4-wide dots per kept (u,v)
    float* outp = out + ((size_t)(b * 162 + cq * 54)) * NPLANE + i * HW + j0;
    const float* wp = &sW4[tx * PSTRIDE];

    #pragma unroll
    for (int v = 0; v < 8; v++) {
        const float4 wa = *reinterpret_cast<const float4*>(wp + v * 8);
        const float4 wb = *reinterpret_cast<const float4*>(wp + v * 8 + 4);
        #pragma unroll
        for (int u = 0; u < 8; u++) {
            const int idx = u * 8 + v;
            if ((SUB_MASK >> idx) & 1ULL) continue;
            const int m = idx - __popcll(SUB_MASK & ((1ULL << idx) - 1ULL));
            float2 val;
            val.x = fmaf(gv[u][0], wa.x, fmaf(gv[u][1], wa.y,
                    fmaf(gv[u][2], wa.z, gv[u][3] * wa.w)));
            val.y = fmaf(gv[u][0], wb.x, fmaf(gv[u][1], wb.y,
                    fmaf(gv[u][2], wb.z, gv[u][3] * wb.w)));
            *reinterpret_cast<float2*>(outp + (size_t)m * NPLANE) = val;
        }
    }
}

// ---------------------------------------------------------------------------
extern "C" void kernel_launch(void* const* d_in, const int* in_sizes, int n_in,
                              void* d_out, int out_size) {
    const float* x = (const float*)d_in[0];   // (16, 3, 112, 112) fp32
    float* out = (float*)d_out;               // (16, 162, 112, 112) fp32

    dim3 block(BX, BY);                       // 224 threads
    dim3 grid(HW / BY, 3, NBATCH);            // (28, 3, 16)
    dct_main_kernel<<<grid, block>>>(x, out);
}